// round 17
// baseline (speedup 1.0000x reference)
#include <cuda_runtime.h>
#include <cuda_fp16.h>

typedef unsigned int u32;

#define E_EDGES 400000
#define NTHR 256
#define ASTR 136
#define WSTR 136

// smem byte offsets (per 64-row CTA): A hi/lo + double-buffered W
#define A_HI 0
#define A_LO 17408
#define W0_OFF 34816
#define W1_OFF 69632
#define SMEM_TOTAL 104448

enum { WE_P2=0, WE_P4, WE_RB1, WE_RB2, WE_LIN, WE_RA1A, WE_RA2A, WE_RA1B, WE_RA2B,
       WE_SBFC, WE_SBF, WE_DOWN, WE_UP, WE_TC0, WE_TC1, WE_TC2, WE_COUNT };

// each entry is the exact smem W image: single fp16, K rows x WSTR stride
#define WENT 17408
__device__ __align__(16) __half g_wb[WE_COUNT * WENT];
__device__ float g_t[(size_t)E_EDGES * 64];

__device__ __forceinline__ u32 smem_u32(const void* p) {
    u32 a; asm("{ .reg .u64 t; cvta.to.shared.u64 t, %1; cvt.u32.u64 %0, t; }" : "=r"(a) : "l"(p));
    return a;
}
__device__ __forceinline__ float siluf(float x) { return __fdividef(x, 1.0f + __expf(-x)); }

__device__ __forceinline__ void ldmA(u32 addr, u32 &r0, u32 &r1, u32 &r2, u32 &r3) {
    asm volatile("ldmatrix.sync.aligned.m8n8.x4.shared.b16 {%0,%1,%2,%3}, [%4];"
                 : "=r"(r0), "=r"(r1), "=r"(r2), "=r"(r3) : "r"(addr));
}
__device__ __forceinline__ void ldmB4f(u32 addr, u32 &r0, u32 &r1, u32 &r2, u32 &r3) {
    asm volatile("ldmatrix.sync.aligned.m8n8.x4.trans.shared.b16 {%0,%1,%2,%3}, [%4];"
                 : "=r"(r0), "=r"(r1), "=r"(r2), "=r"(r3) : "r"(addr));
}
__device__ __forceinline__ void mma16816(float* c, u32 a0, u32 a1, u32 a2, u32 a3, u32 b0, u32 b1) {
    asm volatile("mma.sync.aligned.m16n8k16.row.col.f32.f16.f16.f32 "
                 "{%0,%1,%2,%3},{%4,%5,%6,%7},{%8,%9},{%0,%1,%2,%3};"
                 : "+f"(c[0]), "+f"(c[1]), "+f"(c[2]), "+f"(c[3])
                 : "r"(a0), "r"(a1), "r"(a2), "r"(a3), "r"(b0), "r"(b1));
}
template<int N>
__device__ __forceinline__ void za(float* a) {
    #pragma unroll
    for (int i = 0; i < N; i++) a[i] = 0.f;
}
__device__ __forceinline__ void cpasync16(u32 sa, const void* ga) {
    asm volatile("cp.async.cg.shared.global [%0], [%1], 16;" :: "r"(sa), "l"(ga) : "memory");
}
#define CP_COMMIT() asm volatile("cp.async.commit_group;" ::: "memory")
#define CP_WAIT()   asm volatile("cp.async.wait_group 0;" ::: "memory")

// ---------------- setup: fold, store fp16 smem-image layout ----------------
__global__ void setup_kernel(
    const float* __restrict__ w_p2, const float* __restrict__ w_p4,
    const float* __restrict__ w_sbf1, const float* __restrict__ w_sbf2,
    const float* __restrict__ w_t1, const float* __restrict__ w_t2,
    const float* __restrict__ w_down, const float* __restrict__ w_up,
    const float* __restrict__ rb_w1, const float* __restrict__ rb_w2,
    const float* __restrict__ w_lin,
    const float* __restrict__ ra_w1, const float* __restrict__ ra_w2,
    const float* __restrict__ w_sbf)
{
    int tid = blockIdx.x * blockDim.x + threadIdx.x;
    int nt = gridDim.x * blockDim.x;
    const float* Wsrc[9] = { w_p2, w_p4, rb_w1, rb_w2, w_lin, ra_w1, ra_w2, ra_w1 + 16384, ra_w2 + 16384 };
    const int Went[9] = { WE_P2, WE_P4, WE_RB1, WE_RB2, WE_LIN, WE_RA1A, WE_RA2A, WE_RA1B, WE_RA2B };
    for (int e = 0; e < 9; e++) {
        __half* dst = g_wb + Went[e] * WENT;
        for (int i = tid; i < 16384; i += nt) {   // i = k*128 + n
            int k = i >> 7, n = i & 127;
            dst[k * WSTR + n] = __float2half_rn(Wsrc[e][n * 128 + k]);
        }
    }
    {   // SBFC: K=48(42 valid), N=128 folded
        __half* dst = g_wb + WE_SBFC * WENT;
        for (int i = tid; i < 48 * 128; i += nt) {
            int k = i >> 7, n = i & 127; float v = 0.f;
            if (k < 42) {
                for (int b = 0; b < 8; b++) v += w_sbf2[n * 8 + b] * w_sbf1[b * 42 + k];
            }
            dst[k * WSTR + n] = __float2half_rn(v);
        }
    }
    {   // SBF: K=48, N=128
        __half* dst = g_wb + WE_SBF * WENT;
        for (int i = tid; i < 48 * 128; i += nt) {
            int k = i >> 7, n = i & 127;
            dst[k * WSTR + n] = __float2half_rn((k < 42) ? w_sbf[n * 42 + k] : 0.f);
        }
    }
    {   // DOWN: K=128, N=64
        __half* dst = g_wb + WE_DOWN * WENT;
        for (int i = tid; i < 128 * 64; i += nt) {
            int k = i >> 6, n = i & 63;
            dst[k * WSTR + n] = __float2half_rn(w_down[n * 128 + k]);
        }
    }
    {   // UP: K=64, N=128
        __half* dst = g_wb + WE_UP * WENT;
        for (int i = tid; i < 64 * 128; i += nt) {
            int k = i >> 7, n = i & 127;
            dst[k * WSTR + n] = __float2half_rn(w_up[n * 64 + k]);
        }
    }
    for (int c = 0; c < 3; c++) {   // TC: N=64, K 128/128/48, folded
        int kp = (c < 2) ? 128 : 48;
        __half* dst = g_wb + (WE_TC0 + c) * WENT;
        for (int i = tid; i < kp * 64; i += nt) {
            int k = i >> 6, n = i & 63, kg = c * 128 + k;
            float v = 0.f;
            if (kg < 294) {
                for (int b = 0; b < 8; b++) v += w_t2[n * 8 + b] * w_t1[b * 294 + kg];
            }
            dst[k * WSTR + n] = __float2half_rn(v);
        }
    }
}

// ---------------- staging ----------------
__device__ __forceinline__ void stageW_async(u32 smu, u32 dstoff, int entry, int K) {
    const char* src = (const char*)(g_wb + entry * WENT);
    int nbytes = K * (WSTR * 2);
    for (int i = threadIdx.x * 16; i < nbytes; i += NTHR * 16) {
        cpasync16(smu + dstoff + i, src + i);
    }
    CP_COMMIT();
}
__device__ __forceinline__ void splitA(char* sm, int rr, int col, float a, float b) {
    __half2 h = __floats2half2_rn(a, b);
    float2 hf = __half22float2(h);
    __half2 lo = __floats2half2_rn(a - hf.x, b - hf.y);
    int off = (rr * ASTR + col) * 2;
    *(__half2*)(sm + A_HI + off) = h;
    *(__half2*)(sm + A_LO + off) = lo;
}
// 64-row tile
__device__ __forceinline__ void stage_split(char* sm, const float* __restrict__ src,
                                            int rstride, int kvalid, int npairs) {
    for (int i = threadIdx.x; i < 64 * npairs; i += NTHR) {
        int rr = i / npairs, jp = i - rr * npairs;
        float2 xv = (2 * jp < kvalid) ? *(const float2*)(src + (size_t)rr * rstride + 2 * jp)
                                      : make_float2(0.f, 0.f);
        splitA(sm, rr, 2 * jp, xv.x, xv.y);
    }
}

// ---------------- warp GEMM: 2-pass fp16 split, B fragments reused across passes ----------------
template<int NB>
__device__ __forceinline__ void wgemm(u32 smu, int nk, float* acc, int mrow, int ncol, int lane, u32 woff) {
    u32 aoff = (u32)((mrow + (lane & 15)) * ASTR + ((lane >> 4) << 3)) * 2;
    u32 boff = (u32)((lane & 15) * WSTR + ncol + ((lane >> 4) << 3)) * 2;
    u32 ahB = smu + A_HI + aoff;
    u32 alB = smu + A_LO + aoff;
    u32 bBase = smu + woff + boff;
    for (int kc = 0; kc < nk; kc++) {
        u32 h0, h1, h2, h3, h4, h5, h6, h7;
        u32 l0, l1, l2, l3, l4, l5, l6, l7;
        ldmA(ahB + kc * 32, h0, h1, h2, h3);
        ldmA(ahB + kc * 32 + 16 * ASTR * 2, h4, h5, h6, h7);
        ldmA(alB + kc * 32, l0, l1, l2, l3);
        ldmA(alB + kc * 32 + 16 * ASTR * 2, l4, l5, l6, l7);
        u32 bA = bBase + kc * 16 * WSTR * 2;
        #pragma unroll
        for (int nb2 = 0; nb2 < NB / 2; nb2++) {
            u32 b0, b1, b2, b3;
            ldmB4f(bA + nb2 * 32, b0, b1, b2, b3);
            mma16816(acc + nb2 * 8,                h0, h1, h2, h3, b0, b1);
            mma16816(acc + nb2 * 8,                l0, l1, l2, l3, b0, b1);
            mma16816(acc + nb2 * 8 + 4,            h0, h1, h2, h3, b2, b3);
            mma16816(acc + nb2 * 8 + 4,            l0, l1, l2, l3, b2, b3);
            mma16816(acc + (NB + nb2 * 2) * 4,     h4, h5, h6, h7, b0, b1);
            mma16816(acc + (NB + nb2 * 2) * 4,     l4, l5, l6, l7, b0, b1);
            mma16816(acc + (NB + nb2 * 2 + 1) * 4, h4, h5, h6, h7, b2, b3);
            mma16816(acc + (NB + nb2 * 2 + 1) * 4, l4, l5, l6, l7, b2, b3);
        }
    }
}

// epilogue iteration: lambda gets (rr, col, cc, idx)
template<int NB, typename F>
__device__ __forceinline__ void epi(float* acc, int mrow, int ncol, int lane, F f) {
    #pragma unroll
    for (int mt = 0; mt < 2; mt++)
    #pragma unroll
    for (int nb = 0; nb < NB; nb++) {
        int col = ncol + nb * 8 + (lane & 3) * 2;
        #pragma unroll
        for (int ri = 0; ri < 2; ri++) {
            int rr = mrow + mt * 16 + (lane >> 2) + ri * 8;
            int idx = (mt * NB + nb) * 4 + ri * 2;
            f(rr, col, acc + idx, idx);
        }
    }
}

// ---------------- Kernel A: g_t = silu((silu(x1@Wp4+b)*sbf)@Wdown), 64-row tiles ----------------
extern "C" __global__ void __launch_bounds__(NTHR, 2)
kernelA(const float* __restrict__ x1, const float* __restrict__ sbf0,
        const float* __restrict__ b_p4)
{
    extern __shared__ char sm[];
    u32 smu = smem_u32(sm);
    int tid = threadIdx.x, w = tid >> 5, lane = tid & 31;
    int mrow = (w & 1) * 32, wn = w >> 1;
    int r0 = blockIdx.x * 64;
    float acc[32], P[32];

    stageW_async(smu, W0_OFF, WE_P4, 128);
    stage_split(sm, x1 + (size_t)r0 * 128, 128, 128, 64);
    CP_WAIT(); __syncthreads();
    stageW_async(smu, W1_OFF, WE_SBFC, 48);
    za<32>(acc); wgemm<4>(smu, 8, acc, mrow, wn * 32, lane, W0_OFF);
    __syncthreads();
    epi<4>(acc, mrow, wn * 32, lane, [&](int rr, int col, float* cc, int idx) {
        float2 bb = *(const float2*)(b_p4 + col);
        P[idx] = siluf(cc[0] + bb.x); P[idx + 1] = siluf(cc[1] + bb.y);
    });
    stage_split(sm, sbf0 + (size_t)r0 * 42, 42, 42, 24);
    CP_WAIT(); __syncthreads();
    stageW_async(smu, W0_OFF, WE_DOWN, 128);
    za<32>(acc); wgemm<4>(smu, 3, acc, mrow, wn * 32, lane, W1_OFF);
    __syncthreads();
    epi<4>(acc, mrow, wn * 32, lane, [&](int rr, int col, float* cc, int idx) {
        splitA(sm, rr, col, cc[0] * P[idx], cc[1] * P[idx + 1]);
    });
    CP_WAIT(); __syncthreads();
    za<16>(acc); wgemm<2>(smu, 8, acc, mrow, wn * 16, lane, W0_OFF);
    epi<2>(acc, mrow, wn * 16, lane, [&](int rr, int col, float* cc, int idx) {
        *(float2*)(g_t + (size_t)(r0 + rr) * 64 + col) = make_float2(siluf(cc[0]), siluf(cc[1]));
    });
}

// ---------------- Kernel B: full tail, 64-row tiles, P in registers ----------------
extern "C" __global__ void __launch_bounds__(NTHR, 2)
kernelB(const float* __restrict__ ta, const float* __restrict__ sbf0,
        const int* __restrict__ p_idx, const float* __restrict__ x1,
        const float* __restrict__ b_p2,
        const float* __restrict__ rb_b1, const float* __restrict__ rb_b2,
        const float* __restrict__ b_lin,
        const float* __restrict__ ra_b1, const float* __restrict__ ra_b2,
        float* __restrict__ out)
{
    extern __shared__ char sm[];
    u32 smu = smem_u32(sm);
    int tid = threadIdx.x, w = tid >> 5, lane = tid & 31;
    int mrow = (w & 1) * 32, wn = w >> 1;
    int r0 = blockIdx.x * 64;
    float acc[32], P[32];
    int nc128 = wn * 32, nc64 = wn * 16;

    // G1: x_p2 = silu(x1@Wp2 + b) -> P regs   [cur W0, prefetch TC0->W1]
    stageW_async(smu, W0_OFF, WE_P2, 128);
    stage_split(sm, x1 + (size_t)r0 * 128, 128, 128, 64);
    CP_WAIT(); __syncthreads();
    stageW_async(smu, W1_OFF, WE_TC0, 128);
    za<32>(acc); wgemm<4>(smu, 8, acc, mrow, nc128, lane, W0_OFF);
    __syncthreads();
    epi<4>(acc, mrow, nc128, lane, [&](int rr, int col, float* cc, int idx) {
        float2 bb = *(const float2*)(b_p2 + col);
        P[idx] = siluf(cc[0] + bb.x); P[idx + 1] = siluf(cc[1] + bb.y);
    });
    stage_split(sm, ta + (size_t)r0 * 294 + 0, 294, 128, 64);
    CP_WAIT(); __syncthreads();

    // G2: ta_p chunks (reg-accumulated)   [TC0@W1 pf TC1->W0; TC1@W0 pf TC2->W1; TC2@W1 pf UP->W0]
    stageW_async(smu, W0_OFF, WE_TC1, 128);
    za<16>(acc);
    wgemm<2>(smu, 8, acc, mrow, nc64, lane, W1_OFF);
    __syncthreads();
    stage_split(sm, ta + (size_t)r0 * 294 + 128, 294, 128, 64);
    CP_WAIT(); __syncthreads();
    stageW_async(smu, W1_OFF, WE_TC2, 48);
    wgemm<2>(smu, 8, acc, mrow, nc64, lane, W0_OFF);
    __syncthreads();
    stage_split(sm, ta + (size_t)r0 * 294 + 256, 294, 38, 24);
    CP_WAIT(); __syncthreads();
    stageW_async(smu, W0_OFF, WE_UP, 64);
    wgemm<2>(smu, 3, acc, mrow, nc64, lane, W1_OFF);
    __syncthreads();
    epi<2>(acc, mrow, nc64, lane, [&](int rr, int col, float* cc, int idx) {
        int idxg = p_idx[r0 + rr];
        float2 tv = *(const float2*)(g_t + (size_t)idxg * 64 + col);
        splitA(sm, rr, col, cc[0] * tv.x, cc[1] * tv.y);
    });
    CP_WAIT(); __syncthreads();

    // G3: p1 = silu(g@Wup) + x_p2 -> P regs, A   [UP@W0, pf RB1->W1]
    stageW_async(smu, W1_OFF, WE_RB1, 128);
    za<32>(acc); wgemm<4>(smu, 4, acc, mrow, nc128, lane, W0_OFF);
    __syncthreads();
    epi<4>(acc, mrow, nc128, lane, [&](int rr, int col, float* cc, int idx) {
        float v0 = siluf(cc[0]) + P[idx];
        float v1 = siluf(cc[1]) + P[idx + 1];
        P[idx] = v0; P[idx + 1] = v1;
        splitA(sm, rr, col, v0, v1);
    });
    CP_WAIT(); __syncthreads();

    // G4..G9: current = RB1,RB2,LIN,RA1A,RA2A,RA1B; prefetch = next in chain
    const int pfN[6] = { WE_RB2, WE_LIN, WE_RA1A, WE_RA2A, WE_RA1B, WE_RA2B };
    const float* bs[6] = { rb_b1, rb_b2, b_lin, ra_b1, ra_b2, ra_b1 + 128 };
    #pragma unroll 1
    for (int s = 0; s < 6; s++) {
        u32 cur = (s & 1) ? W0_OFF : W1_OFF;
        u32 pre = (s & 1) ? W1_OFF : W0_OFF;
        stageW_async(smu, pre, pfN[s], 128);
        za<32>(acc); wgemm<4>(smu, 8, acc, mrow, nc128, lane, cur);
        __syncthreads();
        const float* bb_ = bs[s];
        if (s == 0 || s == 3 || s == 5) {           // first half of res block: A = silu(v+b)
            epi<4>(acc, mrow, nc128, lane, [&](int rr, int col, float* cc, int idx) {
                float2 bb = *(const float2*)(bb_ + col);
                splitA(sm, rr, col, siluf(cc[0] + bb.x), siluf(cc[1] + bb.y));
            });
        } else if (s == 1 || s == 4) {              // second half: P += silu(v+b); A = P
            epi<4>(acc, mrow, nc128, lane, [&](int rr, int col, float* cc, int idx) {
                float2 bb = *(const float2*)(bb_ + col);
                float v0 = P[idx] + siluf(cc[0] + bb.x);
                float v1 = P[idx + 1] + siluf(cc[1] + bb.y);
                P[idx] = v0; P[idx + 1] = v1;
                splitA(sm, rr, col, v0, v1);
            });
        } else {                                    // lin: P = silu(v+b) + x1; A = P
            epi<4>(acc, mrow, nc128, lane, [&](int rr, int col, float* cc, int idx) {
                float2 bb = *(const float2*)(bb_ + col);
                float2 xv = *(const float2*)(x1 + (size_t)(r0 + rr) * 128 + col);
                float v0 = siluf(cc[0] + bb.x) + xv.x;
                float v1 = siluf(cc[1] + bb.y) + xv.y;
                P[idx] = v0; P[idx + 1] = v1;
                splitA(sm, rr, col, v0, v1);
            });
        }
        CP_WAIT(); __syncthreads();
    }

    // G10: RA2B (in W1 after s=5) — P += silu(v+b); write p1   [pf SBF->W0]
    stageW_async(smu, W0_OFF, WE_SBF, 48);
    za<32>(acc); wgemm<4>(smu, 8, acc, mrow, nc128, lane, W1_OFF);
    __syncthreads();
    epi<4>(acc, mrow, nc128, lane, [&](int rr, int col, float* cc, int idx) {
        float2 bb = *(const float2*)(ra_b2 + 128 + col);
        float v0 = P[idx] + siluf(cc[0] + bb.x);
        float v1 = P[idx + 1] + siluf(cc[1] + bb.y);
        P[idx] = v0; P[idx + 1] = v1;
        *(float2*)(out + (size_t)(r0 + rr) * 128 + col) = make_float2(v0, v1);
    });
    stage_split(sm, sbf0 + (size_t)r0 * 42, 42, 42, 24);
    CP_WAIT(); __syncthreads();

    // G11: p2 = (sbf0@Wsbf) * p1   [SBF@W0]
    za<32>(acc); wgemm<4>(smu, 3, acc, mrow, nc128, lane, W0_OFF);
    float* out2 = out + (size_t)E_EDGES * 128;
    epi<4>(acc, mrow, nc128, lane, [&](int rr, int col, float* cc, int idx) {
        *(float2*)(out2 + (size_t)(r0 + rr) * 128 + col) = make_float2(cc[0] * P[idx], cc[1] * P[idx + 1]);
    });
}

// ---------------- launch ----------------
extern "C" void kernel_launch(void* const* d_in, const int* in_sizes, int n_in,
                              void* d_out, int out_size)
{
    const float* x1     = (const float*)d_in[0];
    const float* sbf0   = (const float*)d_in[1];
    const float* ta     = (const float*)d_in[2];
    const int*   p_idx  = (const int*)  d_in[3];
    const float* w_p2   = (const float*)d_in[4];
    const float* b_p2   = (const float*)d_in[5];
    const float* w_p4   = (const float*)d_in[6];
    const float* b_p4   = (const float*)d_in[7];
    const float* w_sbf1 = (const float*)d_in[8];
    const float* w_sbf2 = (const float*)d_in[9];
    const float* w_t1   = (const float*)d_in[10];
    const float* w_t2   = (const float*)d_in[11];
    const float* w_down = (const float*)d_in[12];
    const float* w_up   = (const float*)d_in[13];
    const float* rb_w1  = (const float*)d_in[14];
    const float* rb_b1  = (const float*)d_in[15];
    const float* rb_w2  = (const float*)d_in[16];
    const float* rb_b2  = (const float*)d_in[17];
    const float* w_lin  = (const float*)d_in[18];
    const float* b_lin  = (const float*)d_in[19];
    const float* ra_w1  = (const float*)d_in[20];
    const float* ra_b1  = (const float*)d_in[21];
    const float* ra_w2  = (const float*)d_in[22];
    const float* ra_b2  = (const float*)d_in[23];
    const float* w_sbf  = (const float*)d_in[24];
    float* out = (float*)d_out;

    cudaFuncSetAttribute(kernelA, cudaFuncAttributeMaxDynamicSharedMemorySize, SMEM_TOTAL);
    cudaFuncSetAttribute(kernelB, cudaFuncAttributeMaxDynamicSharedMemorySize, SMEM_TOTAL);

    setup_kernel<<<128, 256>>>(w_p2, w_p4, w_sbf1, w_sbf2, w_t1, w_t2, w_down, w_up,
                               rb_w1, rb_w2, w_lin, ra_w1, ra_w2, w_sbf);
    kernelA<<<E_EDGES / 64, NTHR, SMEM_TOTAL>>>(x1, sbf0, b_p4);
    kernelB<<<E_EDGES / 64, NTHR, SMEM_TOTAL>>>(ta, sbf0, p_idx, x1, b_p2,
                                                rb_b1, rb_b2, b_lin, ra_b1, ra_b2, out);
}